// round 8
// baseline (speedup 1.0000x reference)
#include <cuda_runtime.h>
#include <cuda_bf16.h>
#include <cstdint>

// Tree-RNN, bf16x3-split GEMMs on mma.sync tensor cores.
// - Leaf + mid combines (m>=1024): 128x64 tile, 4-stage cp.async ring,
//   hoisted staging addresses.
// - Small combines (m<=512): single-launch in-CTA sliced-K kernel
//   (8 warps = 4 K-slices x 2 N-halves, smem fp32 reduction).

// ---------------- device scratch (no allocation allowed) ----------------
__device__ __nv_bfloat16 g_leaf_hi[8192ull * 4096];
__device__ __nv_bfloat16 g_leaf_lo[8192ull * 4096];
__device__ __nv_bfloat16 g_We_hi[512 * 4096];
__device__ __nv_bfloat16 g_We_lo[512 * 4096];
__device__ __nv_bfloat16 g_Wc_hi[512 * 1024];
__device__ __nv_bfloat16 g_Wc_lo[512 * 1024];
__device__ __nv_bfloat16 g_hA[8192 * 512], g_lA[8192 * 512];
__device__ __nv_bfloat16 g_hB[4096 * 512], g_lB[4096 * 512];

// ---------------- PTX helpers ----------------
__device__ __forceinline__ void mma_bf16(float c[4], const uint32_t a[4],
                                         const uint32_t b0, const uint32_t b1) {
    asm volatile(
        "mma.sync.aligned.m16n8k16.row.col.f32.bf16.bf16.f32 "
        "{%0,%1,%2,%3}, {%4,%5,%6,%7}, {%8,%9}, {%0,%1,%2,%3};\n"
        : "+f"(c[0]), "+f"(c[1]), "+f"(c[2]), "+f"(c[3])
        : "r"(a[0]), "r"(a[1]), "r"(a[2]), "r"(a[3]), "r"(b0), "r"(b1));
}
__device__ __forceinline__ void cp16(uint32_t dst, const void* src, bool p) {
    asm volatile("cp.async.cg.shared.global [%0], [%1], 16, %2;"
                 :: "r"(dst), "l"(src), "r"(p ? 16 : 0));
}
__device__ __forceinline__ void cp_commit() {
    asm volatile("cp.async.commit_group;");
}
template <int N> __device__ __forceinline__ void cp_wait() {
    asm volatile("cp.async.wait_group %0;" :: "n"(N));
}
__device__ __forceinline__ void ldsm4(uint32_t r[4], uint32_t a) {
    asm volatile("ldmatrix.sync.aligned.m8n8.x4.shared.b16 {%0,%1,%2,%3}, [%4];"
                 : "=r"(r[0]), "=r"(r[1]), "=r"(r[2]), "=r"(r[3]) : "r"(a));
}
__device__ __forceinline__ uint32_t pack_bf2(__nv_bfloat16 a, __nv_bfloat16 b) {
    __nv_bfloat162 t{a, b};
    return *reinterpret_cast<uint32_t*>(&t);
}

// ---------------- fp32 -> bf16 hi/lo split (streaming) ----------------
__global__ void split_kernel(const float4* __restrict__ src,
                             uint2* __restrict__ hi, uint2* __restrict__ lo,
                             int n4)
{
    int i = blockIdx.x * blockDim.x + threadIdx.x;
    const int stride = gridDim.x * blockDim.x;
    for (; i < n4; i += stride) {
        float4 v = src[i];
        __nv_bfloat16 h0 = __float2bfloat16(v.x), h1 = __float2bfloat16(v.y);
        __nv_bfloat16 h2 = __float2bfloat16(v.z), h3 = __float2bfloat16(v.w);
        uint2 H, L;
        H.x = pack_bf2(h0, h1);
        H.y = pack_bf2(h2, h3);
        L.x = pack_bf2(__float2bfloat16(v.x - __bfloat162float(h0)),
                       __float2bfloat16(v.y - __bfloat162float(h1)));
        L.y = pack_bf2(__float2bfloat16(v.z - __bfloat162float(h2)),
                       __float2bfloat16(v.w - __bfloat162float(h3)));
        hi[i] = H;
        lo[i] = L;
    }
}

// ============================================================================
// gemm64: 128x64 tile, BK=32, 4-stage ring, hoisted staging addresses.
// ============================================================================
#define A_T1 16384
#define STAGE1 24576
#define SMEM1 (4 * STAGE1)    // 98304

__global__ __launch_bounds__(256, 2)
void gemm64(const __nv_bfloat16* __restrict__ Ahi,
            const __nv_bfloat16* __restrict__ Alo,
            const __nv_bfloat16* __restrict__ Whi,
            const __nv_bfloat16* __restrict__ Wlo,
            const float* __restrict__ bias,
            __nv_bfloat16* __restrict__ Chi,
            __nv_bfloat16* __restrict__ Clo,
            int M, int N, int K)
{
    extern __shared__ __align__(1024) char smem[];
    const uint32_t sbase = (uint32_t)__cvta_generic_to_shared(smem);

    const int tid  = threadIdx.x;
    const int lane = tid & 31;
    const int wid  = tid >> 5;
    const int wm   = (wid & 3) * 32;
    const int wn   = (wid >> 2) * 32;
    const int bm   = blockIdx.y * 128;
    const int bn   = blockIdx.x * 64;

    const int lr8   = lane & 7;
    const int g     = lane >> 3;
    const int mrow  = (g & 1) * 8;
    const int kcolB = (g >> 1) * 16;

    uint32_t aRow[2], aXm[2], bRow[2], bXm[2];
    #pragma unroll
    for (int mi = 0; mi < 2; mi++) {
        const uint32_t rB = (uint32_t)(wm + mi * 16 + mrow + lr8) * 128;
        aRow[mi] = rB;
        aXm[mi]  = (rB >> 3) & 0x70;
    }
    #pragma unroll
    for (int p = 0; p < 2; p++) {
        const uint32_t rB = (uint32_t)(wn + p * 16 + mrow + lr8) * 128;
        bRow[p] = A_T1 + rB;
        bXm[p]  = (rB >> 3) & 0x70;
    }

    // hoisted staging addresses (loop-invariant)
    const __nv_bfloat16* srcA[4];
    uint32_t dstA[4];
    bool predA[4];
    #pragma unroll
    for (int i = 0; i < 4; i++) {
        const int lin = tid + i * 256;
        const int r = lin >> 3;
        const int c = lin & 7;
        const uint32_t off = (uint32_t)r * 128 + (uint32_t)c * 16;
        dstA[i]  = off ^ ((off >> 3) & 0x70);
        predA[i] = (bm + r) < M;
        srcA[i]  = ((c < 4) ? Ahi : Alo) + (size_t)(bm + r) * K + (c & 3) * 8;
    }
    const __nv_bfloat16* srcB[2];
    uint32_t dstB[2];
    #pragma unroll
    for (int i = 0; i < 2; i++) {
        const int lin = tid + i * 256;
        const int r = lin >> 3;
        const int c = lin & 7;
        const uint32_t off = (uint32_t)r * 128 + (uint32_t)c * 16;
        dstB[i] = A_T1 + (off ^ ((off >> 3) & 0x70));
        srcB[i] = ((c < 4) ? Whi : Wlo) + (size_t)(bn + r) * K + (c & 3) * 8;
    }

    float acc[2][4][4];
    #pragma unroll
    for (int i = 0; i < 2; i++)
        #pragma unroll
        for (int j = 0; j < 4; j++)
            #pragma unroll
            for (int v = 0; v < 4; v++) acc[i][j][v] = 0.f;

    const int nT = K / 32;

    auto stage = [&](int lt) {
        const uint32_t sb = sbase + (uint32_t)(lt & 3) * STAGE1;
        const int k0 = lt * 32;
        #pragma unroll
        for (int i = 0; i < 4; i++)
            cp16(sb + dstA[i], srcA[i] + k0, predA[i]);
        #pragma unroll
        for (int i = 0; i < 2; i++)
            cp16(sb + dstB[i], srcB[i] + k0, true);
        cp_commit();
    };

    stage(0);
    stage(1);
    stage(2);

    for (int kt = 0; kt < nT; kt++) {
        if (kt + 2 <= nT - 1)      cp_wait<2>();
        else if (kt + 1 <= nT - 1) cp_wait<1>();
        else                       cp_wait<0>();
        __syncthreads();
        if (kt + 3 < nT) stage(kt + 3);

        const uint32_t s0 = sbase + (uint32_t)(kt & 3) * STAGE1;

        #pragma unroll
        for (int ks = 0; ks < 32; ks += 16) {
            const uint32_t colH = (uint32_t)(ks * 2) + kcolB;
            const uint32_t colL = 64u + (uint32_t)(ks * 2) + kcolB;
            uint32_t ah[2][4], al[2][4], bh[2][4], bl[2][4];
            #pragma unroll
            for (int mi = 0; mi < 2; mi++) {
                ldsm4(ah[mi], s0 + aRow[mi] + (colH ^ aXm[mi]));
                ldsm4(al[mi], s0 + aRow[mi] + (colL ^ aXm[mi]));
            }
            #pragma unroll
            for (int p = 0; p < 2; p++) {
                ldsm4(bh[p], s0 + bRow[p] + (colH ^ bXm[p]));
                ldsm4(bl[p], s0 + bRow[p] + (colL ^ bXm[p]));
            }
            #pragma unroll
            for (int mi = 0; mi < 2; mi++)
                #pragma unroll
                for (int ni = 0; ni < 4; ni++) {
                    const int p = ni >> 1, q = ni & 1;
                    mma_bf16(acc[mi][ni], ah[mi], bh[p][q], bh[p][q + 2]);
                    mma_bf16(acc[mi][ni], ah[mi], bl[p][q], bl[p][q + 2]);
                    mma_bf16(acc[mi][ni], al[mi], bh[p][q], bh[p][q + 2]);
                }
        }
    }

    const int lq = (lane & 3) * 2;
    const int lr = lane >> 2;
    #pragma unroll
    for (int mi = 0; mi < 2; mi++) {
        #pragma unroll
        for (int ni = 0; ni < 4; ni++) {
            const int m0 = bm + wm + mi * 16 + lr;
            const int n  = bn + wn + ni * 8 + lq;
            const float bv0 = __ldg(bias + n), bv1 = __ldg(bias + n + 1);
            #pragma unroll
            for (int h = 0; h < 2; h++) {
                const int m = m0 + h * 8;
                if (m < M) {
                    float x0 = fmaxf(acc[mi][ni][2 * h]     + bv0, 0.f);
                    float x1 = fmaxf(acc[mi][ni][2 * h + 1] + bv1, 0.f);
                    __nv_bfloat16 h0 = __float2bfloat16(x0);
                    __nv_bfloat16 h1 = __float2bfloat16(x1);
                    __nv_bfloat16 l0 = __float2bfloat16(x0 - __bfloat162float(h0));
                    __nv_bfloat16 l1 = __float2bfloat16(x1 - __bfloat162float(h1));
                    *reinterpret_cast<uint32_t*>(Chi + (size_t)m * N + n) = pack_bf2(h0, h1);
                    *reinterpret_cast<uint32_t*>(Clo + (size_t)m * N + n) = pack_bf2(l0, l1);
                }
            }
        }
    }
}

// ============================================================================
// gemm_sliced: small-M kernel, in-CTA sliced-K. 256 threads = 8 warps:
// wk = wid&3 (K-slice), nh = wid>>2 (N-half). Tile 32x64, BK_stage=128.
// Rows are 512B (256B hi | 256B lo); swizzle = 16B-unit ^ (row&7).
// Ends with smem fp32 reduction + bias + relu + hi/lo split. ONE launch.
// ============================================================================
#define AS_T (32 * 512)           // 16384
#define STAGE_S (AS_T + 64 * 512) // 49152
#define SMEM_S (3 * STAGE_S)      // 147456

__global__ __launch_bounds__(256, 1)
void gemm_sliced(const __nv_bfloat16* __restrict__ Ahi,
                 const __nv_bfloat16* __restrict__ Alo,
                 const __nv_bfloat16* __restrict__ Whi,
                 const __nv_bfloat16* __restrict__ Wlo,
                 const float* __restrict__ bias,
                 __nv_bfloat16* __restrict__ Chi,
                 __nv_bfloat16* __restrict__ Clo,
                 int M, int N, int K)
{
    extern __shared__ __align__(1024) char smem[];
    const uint32_t sbase = (uint32_t)__cvta_generic_to_shared(smem);

    const int tid  = threadIdx.x;
    const int lane = tid & 31;
    const int wid  = tid >> 5;
    const int wk   = wid & 3;        // K-slice 0..3 (32 k each within 128)
    const int nh   = wid >> 2;       // N-half 0..1
    const int bm   = blockIdx.y * 32;
    const int bn   = blockIdx.x * 64;

    const int lr8   = lane & 7;
    const int g     = lane >> 3;
    const int mrow  = (g & 1) * 8;
    const int kcolB = (g >> 1) * 16;  // byte offset within k16 frag

    // staging addresses (hoisted). A: 1024 chunks (4/thread), B: 2048 (8/thread)
    const __nv_bfloat16* srcA[4];
    uint32_t dstA[4];
    bool predA[4];
    #pragma unroll
    for (int i = 0; i < 4; i++) {
        const int lin = tid + i * 256;
        const int r = lin >> 5;           // 0..31
        const int cc = lin & 31;
        const int part = cc >> 4;         // 0 hi, 1 lo
        const int k16 = cc & 15;          // chunk: k elems [k16*8, k16*8+8)
        dstA[i] = (uint32_t)r * 512 + part * 256 + (k16 >> 3) * 128
                + (uint32_t)(((k16 & 7) ^ (r & 7)) * 16);
        predA[i] = (bm + r) < M;
        srcA[i]  = (part ? Alo : Ahi) + (size_t)(bm + r) * K + k16 * 8;
    }
    const __nv_bfloat16* srcB[8];
    uint32_t dstB[8];
    #pragma unroll
    for (int i = 0; i < 8; i++) {
        const int lin = tid + i * 256;
        const int r = lin >> 5;           // 0..63
        const int cc = lin & 31;
        const int part = cc >> 4;
        const int k16 = cc & 15;
        dstB[i] = AS_T + (uint32_t)r * 512 + part * 256 + (k16 >> 3) * 128
                + (uint32_t)(((k16 & 7) ^ (r & 7)) * 16);
        srcB[i] = (part ? Wlo : Whi) + (size_t)(bn + r) * K + k16 * 8;
    }

    // frag-load bases: A rows (2 m-frags), B rows (2 n16 blocks of this half)
    uint32_t aR[2], bR[2];
    #pragma unroll
    for (int mi = 0; mi < 2; mi++) {
        const int r = mi * 16 + mrow + lr8;
        aR[mi] = (uint32_t)r * 512 + (uint32_t)((r & 7) * 16);  // xor folded: colU^ (r&7)
    }
    #pragma unroll
    for (int p = 0; p < 2; p++) {
        const int r = nh * 32 + p * 16 + mrow + lr8;
        bR[p] = AS_T + (uint32_t)r * 512 + (uint32_t)((r & 7) * 16);
    }
    // NOTE: xor is (u ^ (r&7))*16 = (u*16) ^ ((r&7)*16) since both 16-aligned
    // and u,r&7 < 8 -> disjoint-safe XOR on bits [4:7).

    float acc[2][4][4];
    #pragma unroll
    for (int i = 0; i < 2; i++)
        #pragma unroll
        for (int j = 0; j < 4; j++)
            #pragma unroll
            for (int v = 0; v < 4; v++) acc[i][j][v] = 0.f;

    const int nT = K / 128;

    auto stage = [&](int lt) {
        const uint32_t sb = sbase + (uint32_t)(lt % 3) * STAGE_S;
        const int k0 = lt * 128;
        #pragma unroll
        for (int i = 0; i < 4; i++)
            cp16(sb + dstA[i], srcA[i] + k0, predA[i]);
        #pragma unroll
        for (int i = 0; i < 8; i++)
            cp16(sb + dstB[i], srcB[i] + k0, true);
        cp_commit();
    };

    stage(0);
    stage(1);

    for (int kt = 0; kt < nT; kt++) {
        if (kt + 1 < nT) cp_wait<1>();
        else             cp_wait<0>();
        __syncthreads();
        if (kt + 2 < nT) stage(kt + 2);

        const uint32_t s0 = sbase + (uint32_t)(kt % 3) * STAGE_S;

        #pragma unroll
        for (int ks = 0; ks < 32; ks += 16) {
            const int kbyte = (wk * 32 + ks) * 2 + kcolB;   // 0..255
            const uint32_t lineOff = (uint32_t)((kbyte >> 7) * 128);
            const uint32_t uH = (uint32_t)(((kbyte >> 4) & 7) * 16);
            // lo part: +256 bytes, same line/u structure
            uint32_t ah[2][4], al[2][4], bh[2][4], bl[2][4];
            #pragma unroll
            for (int mi = 0; mi < 2; mi++) {
                ldsm4(ah[mi], s0 + ((aR[mi] + lineOff) ^ uH));
                ldsm4(al[mi], s0 + ((aR[mi] + 256 + lineOff) ^ uH));
            }
            #pragma unroll
            for (int p = 0; p < 2; p++) {
                ldsm4(bh[p], s0 + ((bR[p] + lineOff) ^ uH));
                ldsm4(bl[p], s0 + ((bR[p] + 256 + lineOff) ^ uH));
            }
            #pragma unroll
            for (int mi = 0; mi < 2; mi++)
                #pragma unroll
                for (int ni = 0; ni < 4; ni++) {
                    const int p = ni >> 1, q = ni & 1;
                    mma_bf16(acc[mi][ni], ah[mi], bh[p][q], bh[p][q + 2]);
                    mma_bf16(acc[mi][ni], ah[mi], bl[p][q], bl[p][q + 2]);
                    mma_bf16(acc[mi][ni], al[mi], bh[p][q], bh[p][q + 2]);
                }
        }
    }

    // ---- cross-warp K reduction in smem ----
    __syncthreads();                       // everyone done with stage reads
    // each warp writes its 32x32 fp32 tile to region wid*4096
    {
        const int lq = (lane & 3) * 2;
        const int lr = lane >> 2;
        float* reg = reinterpret_cast<float*>(smem) + wid * 1024;
        #pragma unroll
        for (int mi = 0; mi < 2; mi++)
            #pragma unroll
            for (int ni = 0; ni < 4; ni++)
                #pragma unroll
                for (int h = 0; h < 2; h++) {
                    const int row = mi * 16 + h * 8 + lr;
                    const int col = ni * 8 + lq;
                    *reinterpret_cast<float2*>(reg + row * 32 + col) =
                        make_float2(acc[mi][ni][2 * h], acc[mi][ni][2 * h + 1]);
                }
    }
    __syncthreads();

    // final: 2048 outputs, 8 per thread (consecutive n)
    {
        const int m  = tid >> 3;                 // 0..31
        const int n0 = (tid & 7) * 8;            // 0..56
        const int half = n0 >> 5;                // region group
        const int c0 = n0 & 31;
        if (bm + m < M) {
            float f[8];
            #pragma unroll
            for (int j = 0; j < 8; j++) f[j] = 0.f;
            #pragma unroll
            for (int w = 0; w < 4; w++) {
                const float* reg = reinterpret_cast<const float*>(smem)
                                 + (half * 4 + w) * 1024 + m * 32 + c0;
                #pragma unroll
                for (int j = 0; j < 8; j++) f[j] += reg[j];
            }
            #pragma unroll
            for (int j = 0; j < 8; j += 2) {
                const int n = bn + n0 + j;
                float x0 = fmaxf(f[j]     + __ldg(bias + n),     0.f);
                float x1 = fmaxf(f[j + 1] + __ldg(bias + n + 1), 0.f);
                __nv_bfloat16 h0 = __float2bfloat16(x0);
                __nv_bfloat16 h1 = __float2bfloat16(x1);
                __nv_bfloat16 l0 = __float2bfloat16(x0 - __bfloat162float(h0));
                __nv_bfloat16 l1 = __float2bfloat16(x1 - __bfloat162float(h1));
                *reinterpret_cast<uint32_t*>(Chi + (size_t)(bm + m) * N + n) = pack_bf2(h0, h1);
                *reinterpret_cast<uint32_t*>(Clo + (size_t)(bm + m) * N + n) = pack_bf2(l0, l1);
            }
        }
    }
}

// Root projection
__global__ void proj_kernel(const __nv_bfloat16* __restrict__ hhi,
                            const __nv_bfloat16* __restrict__ hlo,
                            const float* __restrict__ Wp,
                            const float* __restrict__ bp,
                            float* __restrict__ out)
{
    const int w    = threadIdx.x >> 5;
    const int lane = threadIdx.x & 31;
    float s = 0.f;
    for (int k = lane; k < 512; k += 32) {
        const float hv = __bfloat162float(hhi[k]) + __bfloat162float(hlo[k]);
        s = fmaf(hv, Wp[w * 512 + k], s);
    }
    #pragma unroll
    for (int o = 16; o > 0; o >>= 1)
        s += __shfl_xor_sync(0xffffffffu, s, o);
    if (lane == 0) out[w] = s + bp[w];
}

extern "C" void kernel_launch(void* const* d_in, const int* in_sizes, int n_in,
                              void* d_out, int out_size)
{
    const float* leaf  = (const float*)d_in[0];
    const float* Wemb  = (const float*)d_in[1];
    const float* bemb  = (const float*)d_in[2];
    const float* Wcomb = (const float*)d_in[3];
    const float* bcomb = (const float*)d_in[4];
    const float* Wproj = (const float*)d_in[5];
    const float* bproj = (const float*)d_in[6];
    float* out = (float*)d_out;

    __nv_bfloat16 *leaf_hi, *leaf_lo, *We_hi, *We_lo, *Wc_hi, *Wc_lo;
    __nv_bfloat16 *hA, *lA, *hB, *lB;
    cudaGetSymbolAddress((void**)&leaf_hi, g_leaf_hi);
    cudaGetSymbolAddress((void**)&leaf_lo, g_leaf_lo);
    cudaGetSymbolAddress((void**)&We_hi, g_We_hi);
    cudaGetSymbolAddress((void**)&We_lo, g_We_lo);
    cudaGetSymbolAddress((void**)&Wc_hi, g_Wc_hi);
    cudaGetSymbolAddress((void**)&Wc_lo, g_Wc_lo);
    cudaGetSymbolAddress((void**)&hA, g_hA);
    cudaGetSymbolAddress((void**)&lA, g_lA);
    cudaGetSymbolAddress((void**)&hB, g_hB);
    cudaGetSymbolAddress((void**)&lB, g_lB);

    cudaFuncSetAttribute(gemm64,
                         cudaFuncAttributeMaxDynamicSharedMemorySize, SMEM1);
    cudaFuncSetAttribute(gemm_sliced,
                         cudaFuncAttributeMaxDynamicSharedMemorySize, SMEM_S);

    // ---- pre-split fp32 inputs into bf16 hi/lo ----
    split_kernel<<<4096, 256>>>((const float4*)leaf,
                                (uint2*)leaf_hi, (uint2*)leaf_lo, 8192 * 4096 / 4);
    split_kernel<<<1024, 256>>>((const float4*)Wemb,
                                (uint2*)We_hi, (uint2*)We_lo, 512 * 4096 / 4);
    split_kernel<<<512, 256>>>((const float4*)Wcomb,
                               (uint2*)Wc_hi, (uint2*)Wc_lo, 512 * 1024 / 4);

    // ---- leaf embedding: [8192,4096] @ [512,4096]^T -> hA/lA ----
    {
        dim3 grid(512 / 64, 8192 / 128);
        gemm64<<<grid, 256, SMEM1>>>(leaf_hi, leaf_lo, We_hi, We_lo,
                                     bemb, hA, lA, 8192, 512, 4096);
    }

    // ---- 13 combine levels: [rows,512] viewed as [rows/2,1024] ----
    __nv_bfloat16 *cur_h = hA, *cur_l = lA, *nxt_h = hB, *nxt_l = lB;
    int rows = 8192;
    while (rows > 1) {
        const int m = rows / 2;
        if (m >= 1024) {
            dim3 grid(512 / 64, (m + 127) / 128);
            gemm64<<<grid, 256, SMEM1>>>(cur_h, cur_l, Wc_hi, Wc_lo,
                                         bcomb, nxt_h, nxt_l, m, 512, 1024);
        } else {
            dim3 grid(512 / 64, (m + 31) / 32);
            gemm_sliced<<<grid, 256, SMEM_S>>>(cur_h, cur_l, Wc_hi, Wc_lo,
                                               bcomb, nxt_h, nxt_l, m, 512, 1024);
        }
        __nv_bfloat16* t;
        t = cur_h; cur_h = nxt_h; nxt_h = t;
        t = cur_l; cur_l = nxt_l; nxt_l = t;
        rows = m;
    }

    proj_kernel<<<1, 64>>>(cur_h, cur_l, Wproj, bproj, out);
}